// round 1
// baseline (speedup 1.0000x reference)
#include <cuda_runtime.h>
#include <math.h>

#define FULLMASK 0xffffffffu
#define EPS_REC 1e-4f

// ---------------------------------------------------------------------------
// One-sided Jacobi eigensolver for a symmetric PSD matrix held column-wise
// across warp lanes. Lane j owns column j of G (init A) and of V (init I).
// At convergence G = A*V has columns lambda_j * v_j, so lambda_j = v_j . g_j.
// N = padded size (20/16/4), tournament ordering: fixed player M=N-1,
// round r pairs (M, r) and {j, (2r - j) mod M}. All 32 lanes execute
// (lanes >= N carry zero data and always take the identity-rotation path).
// ---------------------------------------------------------------------------
template<int N>
__device__ __forceinline__ void jacobi_onesided(float (&g)[20], float (&v)[20],
                                                int lane, int max_sweeps)
{
    constexpr int M = N - 1;
    #pragma unroll
    for (int k = 0; k < N; ++k) v[k] = (lane == k) ? 1.0f : 0.0f;

    for (int sweep = 0; sweep < max_sweeps; ++sweep) {
        bool anyrot = false;
        for (int r = 0; r < M; ++r) {
            int partner;
            if (lane >= N)      partner = lane;          // inert lanes self-shuffle
            else if (lane == M) partner = r;
            else if (lane == r) partner = M;
            else                partner = ((2 * r - lane) % M + M) % M;

            float pg[N];
            float a0 = 0.f, a1 = 0.f, d0 = 0.f, d1 = 0.f;
            #pragma unroll
            for (int k = 0; k < N; ++k) {
                pg[k] = __shfl_sync(FULLMASK, g[k], partner);
                if (k & 1) { a1 = fmaf(g[k], g[k], a1); d1 = fmaf(g[k], pg[k], d1); }
                else       { a0 = fmaf(g[k], g[k], a0); d0 = fmaf(g[k], pg[k], d0); }
            }
            float a = a0 + a1;
            float d = d0 + d1;                    // bit-identical on both lanes
            float bb = __shfl_sync(FULLMASK, a, partner);
            bool  lower = lane < partner;
            float app = lower ? a  : bb;
            float aqq = lower ? bb : a;

            bool rot = (d * d > 1e-12f * app * aqq);
            anyrot |= rot;

            float dsafe = rot ? d : 1.0f;
            float tau = (aqq - app) / (2.0f * dsafe);
            float t   = copysignf(1.0f, tau) / (fabsf(tau) + sqrtf(fmaf(tau, tau, 1.0f)));
            float cc  = rsqrtf(fmaf(t, t, 1.0f));
            float ss  = t * cc;
            if (!rot) { cc = 1.0f; ss = 0.0f; }
            float sl = lower ? -ss : ss;

            #pragma unroll
            for (int k = 0; k < N; ++k) {
                float pv = __shfl_sync(FULLMASK, v[k], partner);
                g[k] = fmaf(sl, pg[k], cc * g[k]);
                v[k] = fmaf(sl, pv,    cc * v[k]);
            }
        }
        if (!__any_sync(FULLMASK, anyrot)) break;
    }
}

// ReEig in correction form: m += sum over deficient eigenpairs of
// (eps - lambda_i) * v_i v_i^T  (column `lane` of that outer product).
// Exact pass-through when nothing is clamped.
template<int N, int NREAL>
__device__ __forceinline__ void reeig_correction(float (&m)[20], const float (&g)[20],
                                                 const float (&v)[20], int lane)
{
    float lam = 0.f;
    #pragma unroll
    for (int k = 0; k < N; ++k) lam = fmaf(v[k], g[k], lam);

    bool defic = (lane < NREAL) && (lam < EPS_REC);
    unsigned mask = __ballot_sync(FULLMASK, defic);
    while (mask) {                                // warp-uniform loop
        int i = __ffs(mask) - 1;
        mask &= mask - 1;
        float li   = __shfl_sync(FULLMASK, lam, i);
        float coef = EPS_REC - li;
        float vmy  = 0.f;
        float bv[N];
        #pragma unroll
        for (int k = 0; k < N; ++k) {
            bv[k] = __shfl_sync(FULLMASK, v[k], i);
            vmy   = (lane == k) ? bv[k] : vmy;    // v_i[lane] without dynamic index
        }
        float cf = coef * vmy;
        #pragma unroll
        for (int k = 0; k < N; ++k) m[k] = fmaf(cf, bv[k], m[k]);
    }
}

// ---------------------------------------------------------------------------
// One warp per batch element; 8 warps (8 matrices) per 256-thread block.
// ---------------------------------------------------------------------------
__global__ void __launch_bounds__(256, 2)
spd_net_kernel(const float* __restrict__ x,
               const float* __restrict__ w1,
               const float* __restrict__ w2,
               const float* __restrict__ w3,
               const float* __restrict__ fcw,
               float* __restrict__ out_logp,
               float* __restrict__ out_feat,
               int B)
{
    __shared__ float sw1[361], sw2[304], sw3[64], sfc[32];
    __shared__ float S[8][20][21];                // per-warp matrix scratch

    int tid = threadIdx.x;
    for (int i = tid; i < 361; i += 256) sw1[i] = w1[i];
    for (int i = tid; i < 304; i += 256) sw2[i] = w2[i];
    if (tid < 64) sw3[tid] = w3[tid];
    if (tid < 32) sfc[tid] = fcw[tid];
    __syncthreads();

    int warp = tid >> 5, lane = tid & 31;
    int b = blockIdx.x * 8 + warp;
    if (b >= B) return;
    float (*Sm)[21] = S[warp];

    const float* xb = x + (size_t)b * 361;
    for (int i = lane; i < 361; i += 32) Sm[i / 19][i % 19] = xb[i];
    __syncwarp();

    float m[20], g[20], v[20];

    // ---- stage 1: M1 = w1^T X w1 (column `lane`) ----
    {
        int j = (lane < 19) ? lane : 0;
        float wc[19], t[19];
        #pragma unroll
        for (int k = 0; k < 19; ++k) wc[k] = sw1[k * 19 + j];
        #pragma unroll
        for (int i = 0; i < 19; ++i) {
            float acc = 0.f;
            #pragma unroll
            for (int k = 0; k < 19; ++k) acc = fmaf(Sm[i][k], wc[k], acc);
            t[i] = acc;
        }
        #pragma unroll
        for (int i = 0; i < 19; ++i) {
            float acc = 0.f;
            #pragma unroll
            for (int k = 0; k < 19; ++k) acc = fmaf(sw1[k * 19 + i], t[k], acc);
            m[i] = (lane < 19) ? acc : 0.f;
        }
        m[19] = 0.f;
    }

    // ---- stage 2: ReEig(19x19), padded to 20 ----
    #pragma unroll
    for (int k = 0; k < 20; ++k) g[k] = m[k];
    jacobi_onesided<20>(g, v, lane, 12);
    reeig_correction<20, 19>(m, g, v, lane);

    __syncwarp();
    if (lane < 19) {
        #pragma unroll
        for (int k = 0; k < 19; ++k) Sm[k][lane] = m[k];   // Y1 column
    }
    __syncwarp();

    // ---- stage 3: M2 = w2^T Y1 w2 (16x16, column `lane`) ----
    {
        int j = (lane < 16) ? lane : 0;
        float wc[19], t[19];
        #pragma unroll
        for (int k = 0; k < 19; ++k) wc[k] = sw2[k * 16 + j];
        #pragma unroll
        for (int kk = 0; kk < 19; ++kk) {
            float acc = 0.f;
            #pragma unroll
            for (int r = 0; r < 19; ++r) acc = fmaf(Sm[kk][r], wc[r], acc);
            t[kk] = acc;
        }
        #pragma unroll
        for (int i = 0; i < 16; ++i) {
            float acc = 0.f;
            #pragma unroll
            for (int k = 0; k < 19; ++k) acc = fmaf(sw2[k * 16 + i], t[k], acc);
            m[i] = (lane < 16) ? acc : 0.f;
        }
        #pragma unroll
        for (int i = 16; i < 20; ++i) m[i] = 0.f;
    }

    // ---- stage 4: ReEig(16x16) ----
    #pragma unroll
    for (int k = 0; k < 20; ++k) g[k] = m[k];
    jacobi_onesided<16>(g, v, lane, 12);
    reeig_correction<16, 16>(m, g, v, lane);

    __syncwarp();
    if (lane < 16) {
        #pragma unroll
        for (int k = 0; k < 16; ++k) Sm[k][lane] = m[k];   // Y2 column
    }
    __syncwarp();

    // ---- stage 5: M3 = w3^T Y2 w3 (4x4, column `lane`) ----
    {
        int j = (lane < 4) ? lane : 0;
        float wc[16], t[16];
        #pragma unroll
        for (int k = 0; k < 16; ++k) wc[k] = sw3[k * 4 + j];
        #pragma unroll
        for (int kk = 0; kk < 16; ++kk) {
            float acc = 0.f;
            #pragma unroll
            for (int r = 0; r < 16; ++r) acc = fmaf(Sm[kk][r], wc[r], acc);
            t[kk] = acc;
        }
        #pragma unroll
        for (int i = 0; i < 4; ++i) {
            float acc = 0.f;
            #pragma unroll
            for (int k = 0; k < 16; ++k) acc = fmaf(sw3[k * 4 + i], t[k], acc);
            m[i] = (lane < 4) ? acc : 0.f;
        }
        #pragma unroll
        for (int i = 4; i < 20; ++i) m[i] = 0.f;
    }

    // ---- stage 6: LogEig(4x4), full reconstruction ----
    #pragma unroll
    for (int k = 0; k < 20; ++k) g[k] = m[k];
    jacobi_onesided<4>(g, v, lane, 10);

    float lam = 0.f;
    #pragma unroll
    for (int k = 0; k < 4; ++k) lam = fmaf(v[k], g[k], lam);
    float ll = logf(fmaxf(lam, 1e-30f));

    float c3[4] = {0.f, 0.f, 0.f, 0.f};          // column `lane` of log(X3)
    #pragma unroll
    for (int mm = 0; mm < 4; ++mm) {
        float llm = __shfl_sync(FULLMASK, ll,  mm);
        float bv0 = __shfl_sync(FULLMASK, v[0], mm);
        float bv1 = __shfl_sync(FULLMASK, v[1], mm);
        float bv2 = __shfl_sync(FULLMASK, v[2], mm);
        float bv3 = __shfl_sync(FULLMASK, v[3], mm);
        float vmj = (lane == 0) ? bv0 : (lane == 1) ? bv1 : (lane == 2) ? bv2 : bv3;
        float cf  = llm * vmj;
        c3[0] = fmaf(cf, bv0, c3[0]);
        c3[1] = fmaf(cf, bv1, c3[1]);
        c3[2] = fmaf(cf, bv2, c3[2]);
        c3[3] = fmaf(cf, bv3, c3[3]);
    }
    if (lane >= 4) { c3[0] = c3[1] = c3[2] = c3[3] = 0.f; }

    if (out_feat && lane < 4) {
        #pragma unroll
        for (int i = 0; i < 4; ++i)
            out_feat[(size_t)b * 16 + i * 4 + lane] = c3[i];  // feat = X3 row-major
    }

    if (out_logp) {
        float p0 = 0.f, p1 = 0.f;
        int jj = (lane < 4) ? lane : 0;
        #pragma unroll
        for (int i = 0; i < 4; ++i) {
            int f = i * 4 + jj;
            p0 = fmaf(c3[i], sfc[f * 2 + 0], p0);
            p1 = fmaf(c3[i], sfc[f * 2 + 1], p1);
        }
        p0 += __shfl_xor_sync(FULLMASK, p0, 1);
        p0 += __shfl_xor_sync(FULLMASK, p0, 2);
        p1 += __shfl_xor_sync(FULLMASK, p1, 1);
        p1 += __shfl_xor_sync(FULLMASK, p1, 2);
        if (lane == 0) {
            float mx  = fmaxf(p0, p1);
            float lse = mx + logf(expf(p0 - mx) + expf(p1 - mx));
            out_logp[(size_t)b * 2 + 0] = p0 - lse;
            out_logp[(size_t)b * 2 + 1] = p1 - lse;
        }
    }
}

extern "C" void kernel_launch(void* const* d_in, const int* in_sizes, int n_in,
                              void* d_out, int out_size)
{
    const float* x   = (const float*)d_in[0];
    const float* w1  = (const float*)d_in[1];
    const float* w2  = (const float*)d_in[2];
    const float* w3  = (const float*)d_in[3];
    const float* fcw = (const float*)d_in[4];
    int B = in_sizes[0] / 361;

    float* out  = (float*)d_out;
    float* logp = nullptr;
    float* feat = nullptr;
    if (out_size == 18 * B)      { logp = out; feat = out + (size_t)2 * B; }
    else if (out_size == 2 * B)  { logp = out; }
    else if (out_size == 16 * B) { feat = out; }
    else                         { logp = out; feat = out + (size_t)2 * B; }

    int blocks = (B + 7) / 8;
    spd_net_kernel<<<blocks, 256>>>(x, w1, w2, w3, fcw, logp, feat, B);
}

// round 2
// speedup vs baseline: 14.1954x; 14.1954x over previous
#include <cuda_runtime.h>
#include <math.h>

#define FULLMASK 0xffffffffu
#define EPS_REC 1e-4f

// ---------------------------------------------------------------------------
// Warp-parallel Cholesky test on C = M - eps*I (lane j owns column j, rows
// 0..NR-1 in c[]). Returns true iff all pivots positive, i.e. lambda_min > eps,
// i.e. ReEig is the identity and Jacobi can be skipped. All broadcasts come
// from lanes < NR, so junk on lanes >= NR is harmless. `ok` is warp-uniform.
// ---------------------------------------------------------------------------
template<int NR>
__device__ __forceinline__ bool chol_test(const float (&m)[20], int lane)
{
    float c[NR];
    #pragma unroll
    for (int k = 0; k < NR; ++k) c[k] = (lane == k) ? (m[k] - EPS_REC) : m[k];

    bool ok = true;
    #pragma unroll
    for (int k = 0; k < NR; ++k) {
        float ckk = __shfl_sync(FULLMASK, c[k], k);   // pivot (warp-uniform)
        if (ckk <= 1e-12f) { ok = false; break; }
        float inv  = __fdividef(1.0f, ckk);
        float gmul = c[k] * inv;                       // L[j][k]/sqrt(ckk) scaled
        #pragma unroll
        for (int i = k + 1; i < NR; ++i) {
            float pk = __shfl_sync(FULLMASK, c[i], k); // column k, row i
            c[i] = fmaf(-pk, gmul, c[i]);
        }
    }
    return ok;
}

// ---------------------------------------------------------------------------
// One-sided Jacobi eigensolver; lane j owns column j of G (init A) and V
// (init I). At convergence lambda_j = v_j . g_j. Tournament ordering.
// ---------------------------------------------------------------------------
template<int N>
__device__ __forceinline__ void jacobi_onesided(float (&g)[20], float (&v)[20],
                                                int lane, int max_sweeps)
{
    constexpr int M = N - 1;
    #pragma unroll
    for (int k = 0; k < N; ++k) v[k] = (lane == k) ? 1.0f : 0.0f;

    for (int sweep = 0; sweep < max_sweeps; ++sweep) {
        bool anyrot = false;
        for (int r = 0; r < M; ++r) {
            int partner;
            if (lane >= N)      partner = lane;
            else if (lane == M) partner = r;
            else if (lane == r) partner = M;
            else                partner = ((2 * r - lane) % M + M) % M;

            float pg[N];
            float a0 = 0.f, a1 = 0.f, a2 = 0.f, a3 = 0.f;
            float d0 = 0.f, d1 = 0.f, d2 = 0.f, d3 = 0.f;
            #pragma unroll
            for (int k = 0; k < N; ++k) {
                pg[k] = __shfl_sync(FULLMASK, g[k], partner);
                switch (k & 3) {
                    case 0: a0 = fmaf(g[k], g[k], a0); d0 = fmaf(g[k], pg[k], d0); break;
                    case 1: a1 = fmaf(g[k], g[k], a1); d1 = fmaf(g[k], pg[k], d1); break;
                    case 2: a2 = fmaf(g[k], g[k], a2); d2 = fmaf(g[k], pg[k], d2); break;
                    default:a3 = fmaf(g[k], g[k], a3); d3 = fmaf(g[k], pg[k], d3); break;
                }
            }
            float a = (a0 + a1) + (a2 + a3);
            float d = (d0 + d1) + (d2 + d3);      // bit-identical on both lanes
            float bb = __shfl_sync(FULLMASK, a, partner);
            bool  lower = lane < partner;
            float app = lower ? a  : bb;
            float aqq = lower ? bb : a;

            bool rot = (d * d > 1e-12f * app * aqq);
            anyrot |= rot;

            float dsafe = rot ? d : 1.0f;
            // fast-math rotation: tau, t = sign(tau)/(|tau|+sqrt(tau^2+1))
            float tau = __fdividef(aqq - app, 2.0f * dsafe);
            float t   = __fdividef(copysignf(1.0f, tau),
                                   fabsf(tau) + __fsqrt_rn(fmaf(tau, tau, 1.0f)));
            float cc  = __frsqrt_rn(fmaf(t, t, 1.0f));
            float ss  = t * cc;
            if (!rot) { cc = 1.0f; ss = 0.0f; }
            float sl = lower ? -ss : ss;

            #pragma unroll
            for (int k = 0; k < N; ++k) {
                float pv = __shfl_sync(FULLMASK, v[k], partner);
                g[k] = fmaf(sl, pg[k], cc * g[k]);
                v[k] = fmaf(sl, pv,    cc * v[k]);
            }
        }
        if (!__any_sync(FULLMASK, anyrot)) break;
    }
}

// ReEig in correction form: m += (eps - lambda_i) v_i v_i^T over deficient pairs.
template<int N, int NREAL>
__device__ __forceinline__ void reeig_correction(float (&m)[20], const float (&g)[20],
                                                 const float (&v)[20], int lane)
{
    float lam = 0.f;
    #pragma unroll
    for (int k = 0; k < N; ++k) lam = fmaf(v[k], g[k], lam);

    bool defic = (lane < NREAL) && (lam < EPS_REC);
    unsigned mask = __ballot_sync(FULLMASK, defic);
    while (mask) {
        int i = __ffs(mask) - 1;
        mask &= mask - 1;
        float li   = __shfl_sync(FULLMASK, lam, i);
        float coef = EPS_REC - li;
        float vmy  = 0.f;
        float bv[N];
        #pragma unroll
        for (int k = 0; k < N; ++k) {
            bv[k] = __shfl_sync(FULLMASK, v[k], i);
            vmy   = (lane == k) ? bv[k] : vmy;
        }
        float cf = coef * vmy;
        #pragma unroll
        for (int k = 0; k < N; ++k) m[k] = fmaf(cf, bv[k], m[k]);
    }
}

// ---------------------------------------------------------------------------
// One warp per batch element; 8 warps per 256-thread block.
// ---------------------------------------------------------------------------
__global__ void __launch_bounds__(256, 2)
spd_net_kernel(const float* __restrict__ x,
               const float* __restrict__ w1,
               const float* __restrict__ w2,
               const float* __restrict__ w3,
               const float* __restrict__ fcw,
               float* __restrict__ out_logp,
               float* __restrict__ out_feat,
               int B)
{
    __shared__ float sw1[361], sw2[304], sw3[64], sfc[32];
    __shared__ float S[8][20][21];

    int tid = threadIdx.x;
    for (int i = tid; i < 361; i += 256) sw1[i] = w1[i];
    for (int i = tid; i < 304; i += 256) sw2[i] = w2[i];
    if (tid < 64) sw3[tid] = w3[tid];
    if (tid < 32) sfc[tid] = fcw[tid];
    __syncthreads();

    int warp = tid >> 5, lane = tid & 31;
    int b = blockIdx.x * 8 + warp;
    if (b >= B) return;
    float (*Sm)[21] = S[warp];

    const float* xb = x + (size_t)b * 361;
    for (int i = lane; i < 361; i += 32) Sm[i / 19][i % 19] = xb[i];
    __syncwarp();

    float m[20], g[20], v[20];

    // ---- stage 1: M1 = w1^T X w1 (column `lane`) ----
    {
        int j = (lane < 19) ? lane : 0;
        float wc[19], t[19];
        #pragma unroll
        for (int k = 0; k < 19; ++k) wc[k] = sw1[k * 19 + j];
        #pragma unroll
        for (int i = 0; i < 19; ++i) {
            float acc = 0.f;
            #pragma unroll
            for (int k = 0; k < 19; ++k) acc = fmaf(Sm[i][k], wc[k], acc);
            t[i] = acc;
        }
        #pragma unroll
        for (int i = 0; i < 19; ++i) {
            float acc = 0.f;
            #pragma unroll
            for (int k = 0; k < 19; ++k) acc = fmaf(sw1[k * 19 + i], t[k], acc);
            m[i] = (lane < 19) ? acc : 0.f;
        }
        m[19] = 0.f;
    }

    // ---- stage 2: ReEig(19x19) — Cholesky fast path, Jacobi fallback ----
    if (!chol_test<19>(m, lane)) {
        #pragma unroll
        for (int k = 0; k < 20; ++k) g[k] = m[k];
        jacobi_onesided<20>(g, v, lane, 12);
        reeig_correction<20, 19>(m, g, v, lane);
    }

    __syncwarp();
    if (lane < 19) {
        #pragma unroll
        for (int k = 0; k < 19; ++k) Sm[k][lane] = m[k];
    }
    __syncwarp();

    // ---- stage 3: M2 = w2^T Y1 w2 (16x16) ----
    {
        int j = (lane < 16) ? lane : 0;
        float wc[19], t[19];
        #pragma unroll
        for (int k = 0; k < 19; ++k) wc[k] = sw2[k * 16 + j];
        #pragma unroll
        for (int kk = 0; kk < 19; ++kk) {
            float acc = 0.f;
            #pragma unroll
            for (int r = 0; r < 19; ++r) acc = fmaf(Sm[kk][r], wc[r], acc);
            t[kk] = acc;
        }
        #pragma unroll
        for (int i = 0; i < 16; ++i) {
            float acc = 0.f;
            #pragma unroll
            for (int k = 0; k < 19; ++k) acc = fmaf(sw2[k * 16 + i], t[k], acc);
            m[i] = (lane < 16) ? acc : 0.f;
        }
        #pragma unroll
        for (int i = 16; i < 20; ++i) m[i] = 0.f;
    }

    // ---- stage 4: ReEig(16x16) — Cholesky fast path, Jacobi fallback ----
    if (!chol_test<16>(m, lane)) {
        #pragma unroll
        for (int k = 0; k < 20; ++k) g[k] = m[k];
        jacobi_onesided<16>(g, v, lane, 12);
        reeig_correction<16, 16>(m, g, v, lane);
    }

    __syncwarp();
    if (lane < 16) {
        #pragma unroll
        for (int k = 0; k < 16; ++k) Sm[k][lane] = m[k];
    }
    __syncwarp();

    // ---- stage 5: M3 = w3^T Y2 w3 (4x4) ----
    {
        int j = (lane < 4) ? lane : 0;
        float wc[16], t[16];
        #pragma unroll
        for (int k = 0; k < 16; ++k) wc[k] = sw3[k * 4 + j];
        #pragma unroll
        for (int kk = 0; kk < 16; ++kk) {
            float acc = 0.f;
            #pragma unroll
            for (int r = 0; r < 16; ++r) acc = fmaf(Sm[kk][r], wc[r], acc);
            t[kk] = acc;
        }
        #pragma unroll
        for (int i = 0; i < 4; ++i) {
            float acc = 0.f;
            #pragma unroll
            for (int k = 0; k < 16; ++k) acc = fmaf(sw3[k * 4 + i], t[k], acc);
            m[i] = (lane < 4) ? acc : 0.f;
        }
        #pragma unroll
        for (int i = 4; i < 20; ++i) m[i] = 0.f;
    }

    // ---- stage 6: LogEig(4x4) ----
    #pragma unroll
    for (int k = 0; k < 20; ++k) g[k] = m[k];
    jacobi_onesided<4>(g, v, lane, 10);

    float lam = 0.f;
    #pragma unroll
    for (int k = 0; k < 4; ++k) lam = fmaf(v[k], g[k], lam);
    float ll = logf(fmaxf(lam, 1e-30f));

    float c3[4] = {0.f, 0.f, 0.f, 0.f};
    #pragma unroll
    for (int mm = 0; mm < 4; ++mm) {
        float llm = __shfl_sync(FULLMASK, ll,  mm);
        float bv0 = __shfl_sync(FULLMASK, v[0], mm);
        float bv1 = __shfl_sync(FULLMASK, v[1], mm);
        float bv2 = __shfl_sync(FULLMASK, v[2], mm);
        float bv3 = __shfl_sync(FULLMASK, v[3], mm);
        float vmj = (lane == 0) ? bv0 : (lane == 1) ? bv1 : (lane == 2) ? bv2 : bv3;
        float cf  = llm * vmj;
        c3[0] = fmaf(cf, bv0, c3[0]);
        c3[1] = fmaf(cf, bv1, c3[1]);
        c3[2] = fmaf(cf, bv2, c3[2]);
        c3[3] = fmaf(cf, bv3, c3[3]);
    }
    if (lane >= 4) { c3[0] = c3[1] = c3[2] = c3[3] = 0.f; }

    if (out_feat && lane < 4) {
        #pragma unroll
        for (int i = 0; i < 4; ++i)
            out_feat[(size_t)b * 16 + i * 4 + lane] = c3[i];
    }

    if (out_logp) {
        float p0 = 0.f, p1 = 0.f;
        int jj = (lane < 4) ? lane : 0;
        #pragma unroll
        for (int i = 0; i < 4; ++i) {
            int f = i * 4 + jj;
            p0 = fmaf(c3[i], sfc[f * 2 + 0], p0);
            p1 = fmaf(c3[i], sfc[f * 2 + 1], p1);
        }
        p0 += __shfl_xor_sync(FULLMASK, p0, 1);
        p0 += __shfl_xor_sync(FULLMASK, p0, 2);
        p1 += __shfl_xor_sync(FULLMASK, p1, 1);
        p1 += __shfl_xor_sync(FULLMASK, p1, 2);
        if (lane == 0) {
            float mx  = fmaxf(p0, p1);
            float lse = mx + logf(expf(p0 - mx) + expf(p1 - mx));
            out_logp[(size_t)b * 2 + 0] = p0 - lse;
            out_logp[(size_t)b * 2 + 1] = p1 - lse;
        }
    }
}

extern "C" void kernel_launch(void* const* d_in, const int* in_sizes, int n_in,
                              void* d_out, int out_size)
{
    const float* x   = (const float*)d_in[0];
    const float* w1  = (const float*)d_in[1];
    const float* w2  = (const float*)d_in[2];
    const float* w3  = (const float*)d_in[3];
    const float* fcw = (const float*)d_in[4];
    int B = in_sizes[0] / 361;

    float* out  = (float*)d_out;
    float* logp = nullptr;
    float* feat = nullptr;
    if (out_size == 18 * B)      { logp = out; feat = out + (size_t)2 * B; }
    else if (out_size == 2 * B)  { logp = out; }
    else if (out_size == 16 * B) { feat = out; }
    else                         { logp = out; feat = out + (size_t)2 * B; }

    int blocks = (B + 7) / 8;
    spd_net_kernel<<<blocks, 256>>>(x, w1, w2, w3, fcw, logp, feat, B);
}